// round 1
// baseline (speedup 1.0000x reference)
#include <cuda_runtime.h>

#define BB 2
#define C 64
#define H 64
#define W 64
#define L 4096   // H*W
#define F 576    // C*9
#define HP 66    // H+2 (reflect-padded)

// ---------------- scratch (static device arrays; no allocation) ----------------
__device__ float g_xpad[BB*C*HP*HP];   // reflect-padded x
__device__ float g_h1[BB*C*L];         // relu(conv1)
__device__ float g_feat[BB*C*L];       // conv2 output
__device__ float g_rnorm[BB*L];        // 1/norm per patch column
__device__ float g_un[BB*F*L];         // normalized unfold, [b][f][q], q contiguous
__device__ float g_tv[BB*L*3];         // top-3 values per query
__device__ int   g_ti[BB*L*3];         // top-3 indices per query
__device__ float g_Tcat[BB*2*C*L];     // scaled folded textures (t=2 then t=3)
__device__ float g_tex[BB*C*L];        // 1x1 conv of Tcat

// ---------------- reflect pad ----------------
__global__ void k_xpad(const float* __restrict__ x) {
    int idx = blockIdx.x * blockDim.x + threadIdx.x;
    const int total = BB*C*HP*HP;
    if (idx >= total) return;
    int xx = idx % HP; int t = idx / HP;
    int yy = t % HP;   t /= HP;
    int c  = t % C;    int b = t / C;
    int sy = yy - 1; sy = sy < 0 ? -sy : (sy > H-1 ? 2*(H-1)-sy : sy);
    int sx = xx - 1; sx = sx < 0 ? -sx : (sx > W-1 ? 2*(W-1)-sx : sx);
    g_xpad[idx] = x[((b*C + c)*H + sy)*W + sx];
}

// ---------------- 3x3 conv (zero pad), optional relu ----------------
// grid: (16 tiles, 4 oc-chunks, B), block 256 (16x16 pixels). ic chunked by 16.
__global__ void __launch_bounds__(256) k_conv3x3(
    const float* __restrict__ xin, const float* __restrict__ w,
    const float* __restrict__ bias, int relu, int insel, int outsel)
{
    __shared__ float s_in[16][324];   // 16 ic x 18x18
    __shared__ float s_w[16][144];    // 16 oc x 16 ic x 9

    const float* in = insel ? g_h1 : xin;
    float* out = outsel ? g_feat : g_h1;

    int tile = blockIdx.x;
    int oc0  = blockIdx.y * 16;
    int b    = blockIdx.z;
    int ty0 = (tile / 4) * 16, tx0 = (tile % 4) * 16;
    int tid = threadIdx.x;
    int py = tid / 16, px = tid % 16;

    float acc[16];
    #pragma unroll
    for (int o = 0; o < 16; o++) acc[o] = bias[oc0 + o];

    for (int icc = 0; icc < 4; icc++) {
        for (int i = tid; i < 16*324; i += 256) {
            int ic = i / 324; int rem = i % 324;
            int yy = rem / 18, xx = rem % 18;
            int gy = ty0 + yy - 1, gx = tx0 + xx - 1;
            float v = 0.f;
            if (gy >= 0 && gy < H && gx >= 0 && gx < W)
                v = in[((b*C + icc*16 + ic)*H + gy)*W + gx];
            s_in[ic][rem] = v;
        }
        for (int i = tid; i < 16*144; i += 256) {
            int o = i / 144; int rem = i % 144;
            s_w[o][rem] = w[((oc0 + o)*C + icc*16 + rem/9)*9 + rem%9];
        }
        __syncthreads();

        for (int ic = 0; ic < 16; ic++) {
            float v[9];
            #pragma unroll
            for (int dy = 0; dy < 3; dy++)
                #pragma unroll
                for (int dx = 0; dx < 3; dx++)
                    v[dy*3+dx] = s_in[ic][(py+dy)*18 + px+dx];
            #pragma unroll
            for (int o = 0; o < 16; o++) {
                float a = acc[o];
                #pragma unroll
                for (int k = 0; k < 9; k++) a += v[k] * s_w[o][ic*9 + k];
                acc[o] = a;
            }
        }
        __syncthreads();
    }
    int gy = ty0 + py, gx = tx0 + px;
    #pragma unroll
    for (int o = 0; o < 16; o++) {
        float v = acc[o];
        if (relu) v = fmaxf(v, 0.f);
        out[((b*C + oc0 + o)*H + gy)*W + gx] = v;
    }
}

// ---------------- patch norms ----------------
__global__ void k_norm() {
    int idx = blockIdx.x * blockDim.x + threadIdx.x;   // b*L + q
    if (idx >= BB*L) return;
    int b = idx / L, q = idx % L;
    int qy = q / W, qx = q % W;
    const float* base = &g_xpad[(size_t)b*C*HP*HP];
    float s = 0.f;
    for (int c = 0; c < C; c++) {
        const float* p = base + c*HP*HP + qy*HP + qx;
        #pragma unroll
        for (int i = 0; i < 3; i++)
            #pragma unroll
            for (int j = 0; j < 3; j++) { float v = p[i*HP + j]; s += v*v; }
    }
    float n = sqrtf(s);
    g_rnorm[idx] = 1.f / fmaxf(n, 1e-12f);
}

// ---------------- build normalized unfold un[b][f][q] ----------------
__global__ void k_un() {
    int idx = blockIdx.x * blockDim.x + threadIdx.x;
    if (idx >= BB*F*L) return;
    int q = idx % L; int t = idx / L;
    int f = t % F;   int b = t / F;
    int c = f / 9, k = f % 9;
    int i = k / 3, j = k % 3;
    int qy = q / W, qx = q % W;
    float v = g_xpad[((b*C + c)*HP + qy + i)*HP + qx + j];
    g_un[idx] = v * g_rnorm[b*L + q];
}

// ---------------- fused Gram GEMM + streaming top-3 ----------------
// grid: (64 query-tiles, B). block 256. 64 queries x all 4096 keys.
__global__ void __launch_bounds__(256) k_gemm_topk() {
    __shared__ float As[16][64];
    __shared__ float Bs[16][64];
    __shared__ float Cs[64][65];   // +1 pad: conflict-free column scans

    int b  = blockIdx.y;
    int q0 = blockIdx.x * 64;
    int tid = threadIdx.x;
    int tx = tid % 16, ty = tid / 16;
    const float* un = &g_un[(size_t)b*F*L];

    float v0=-2.f, v1=-2.f, v2=-2.f;
    int   i0=-1,   i1=-1,   i2=-1;

    for (int n0 = 0; n0 < L; n0 += 64) {
        float cr[4][4];
        #pragma unroll
        for (int r = 0; r < 4; r++)
            #pragma unroll
            for (int c = 0; c < 4; c++) cr[r][c] = 0.f;

        for (int kk = 0; kk < F; kk += 16) {
            #pragma unroll
            for (int r = 0; r < 4; r++) {
                int i = tid + r*256;
                int row = i >> 6, col = i & 63;
                As[row][col] = un[(kk + row)*L + q0 + col];
                Bs[row][col] = un[(kk + row)*L + n0 + col];
            }
            __syncthreads();
            #pragma unroll
            for (int p = 0; p < 16; p++) {
                float4 a4 = *(const float4*)&As[p][ty*4];
                float4 b4 = *(const float4*)&Bs[p][tx*4];
                float a[4] = {a4.x, a4.y, a4.z, a4.w};
                float bb[4] = {b4.x, b4.y, b4.z, b4.w};
                #pragma unroll
                for (int r = 0; r < 4; r++)
                    #pragma unroll
                    for (int c = 0; c < 4; c++)
                        cr[r][c] += a[r] * bb[c];
            }
            __syncthreads();
        }
        #pragma unroll
        for (int r = 0; r < 4; r++)
            #pragma unroll
            for (int c = 0; c < 4; c++)
                Cs[ty*4 + r][tx*4 + c] = cr[r][c];
        __syncthreads();

        if (tid < 64) {
            // scan keys in increasing order; strict > matches lax.top_k ties
            #pragma unroll 4
            for (int k = 0; k < 64; k++) {
                float val = Cs[tid][k];
                if (val > v2) {
                    int ki = n0 + k;
                    if (val > v0)      { v2=v1; i2=i1; v1=v0; i1=i0; v0=val; i0=ki; }
                    else if (val > v1) { v2=v1; i2=i1; v1=val; i1=ki; }
                    else               { v2=val; i2=ki; }
                }
            }
        }
        __syncthreads();
    }
    if (tid < 64) {
        int q = q0 + tid;
        g_tv[(b*L + q)*3 + 0] = v0; g_tv[(b*L + q)*3 + 1] = v1; g_tv[(b*L + q)*3 + 2] = v2;
        g_ti[(b*L + q)*3 + 0] = i0; g_ti[(b*L + q)*3 + 1] = i1; g_ti[(b*L + q)*3 + 2] = i2;
    }
}

// ---------------- gather + fold3 + scale (both t in one grid dim) ----------------
// grid: (16 tiles, 2 t, B), block 256 (16x16 pixels)
__global__ void k_fold() {
    int tile = blockIdx.x;
    int tt   = blockIdx.y;        // 0 -> TOPK=2 (slot 1), 1 -> TOPK=3 (slot 2)
    int b    = blockIdx.z;
    int tid = threadIdx.x;
    int py = tid / 16, px = tid % 16;
    int y = (tile / 4)*16 + py, x = (tile % 4)*16 + px;
    int q = y*W + x;
    int slot = tt + 1;

    float S = g_tv[(b*L + q)*3 + slot];

    int off[9];
    #pragma unroll
    for (int i = 0; i < 3; i++) {
        #pragma unroll
        for (int j = 0; j < 3; j++) {
            int h = y + 1 - i, w = x + 1 - j;
            int o = -1;
            if (h >= 0 && h < H && w >= 0 && w < W) {
                int r = g_ti[(b*L + h*W + w)*3 + slot];
                int ry = r / W, rx = r % W;
                o = (ry + i)*HP + (rx + j);
            }
            off[i*3 + j] = o;
        }
    }
    float scale = S * (1.f/9.f);
    const float* xp = &g_xpad[(size_t)b*C*HP*HP];
    float* out = &g_Tcat[(size_t)((b*2 + tt)*C)*L];
    for (int c = 0; c < C; c++) {
        const float* pc = xp + c*HP*HP;
        float s = 0.f;
        #pragma unroll
        for (int k = 0; k < 9; k++)
            if (off[k] >= 0) s += pc[off[k]];
        out[c*L + q] = s * scale;
    }
}

// ---------------- texture 1x1 conv: (64 x 128) ----------------
__global__ void __launch_bounds__(256) k_tex(const float* __restrict__ wt1,
                                             const float* __restrict__ bt1) {
    __shared__ float s_w[64*128];
    for (int i = threadIdx.x; i < 64*128; i += 256) s_w[i] = wt1[i];
    __syncthreads();
    int b = blockIdx.y;
    int p = blockIdx.x*256 + threadIdx.x;
    const float* in = &g_Tcat[(size_t)b*128*L];
    float acc[64];
    #pragma unroll
    for (int o = 0; o < 64; o++) acc[o] = bt1[o];
    for (int k = 0; k < 128; k++) {
        float v = in[k*L + p];
        #pragma unroll
        for (int o = 0; o < 64; o++) acc[o] += v * s_w[o*128 + k];
    }
    float* out = &g_tex[(size_t)b*64*L];
    #pragma unroll
    for (int o = 0; o < 64; o++) out[o*L + p] = acc[o];
}

// ---------------- final 1x1 conv over [feature, x, texture] (64 x 192) ----------------
__global__ void __launch_bounds__(256) k_final(const float* __restrict__ x,
                                               const float* __restrict__ wt2,
                                               const float* __restrict__ bt2,
                                               float* __restrict__ out) {
    __shared__ float s_w[64*64];
    int b = blockIdx.y;
    int p = blockIdx.x*256 + threadIdx.x;
    float acc[64];
    #pragma unroll
    for (int o = 0; o < 64; o++) acc[o] = bt2[o];

    const float* srcs[3] = { &g_feat[(size_t)b*64*L], x + (size_t)b*64*L, &g_tex[(size_t)b*64*L] };
    for (int g = 0; g < 3; g++) {
        __syncthreads();
        for (int i = threadIdx.x; i < 64*64; i += 256) {
            int o = i / 64, k = i % 64;
            s_w[i] = wt2[o*192 + g*64 + k];
        }
        __syncthreads();
        const float* in = srcs[g];
        for (int k = 0; k < 64; k++) {
            float v = in[k*L + p];
            #pragma unroll
            for (int o = 0; o < 64; o++) acc[o] += v * s_w[o*64 + k];
        }
    }
    #pragma unroll
    for (int o = 0; o < 64; o++) out[((size_t)b*64 + o)*L + p] = acc[o];
}

// ---------------- host launcher (graph-capturable; kernel launches only) ----------------
extern "C" void kernel_launch(void* const* d_in, const int* in_sizes, int n_in,
                              void* d_out, int out_size) {
    const float* x   = (const float*)d_in[0];
    const float* w1  = (const float*)d_in[1];
    const float* b1  = (const float*)d_in[2];
    const float* w2  = (const float*)d_in[3];
    const float* b2  = (const float*)d_in[4];
    const float* wt1 = (const float*)d_in[5];
    const float* bt1 = (const float*)d_in[6];
    const float* wt2 = (const float*)d_in[7];
    const float* bt2 = (const float*)d_in[8];
    float* out = (float*)d_out;

    k_xpad<<<(BB*C*HP*HP + 255)/256, 256>>>(x);
    k_conv3x3<<<dim3(16, 4, BB), 256>>>(x, w1, b1, 1, 0, 0);   // x -> relu -> g_h1
    k_conv3x3<<<dim3(16, 4, BB), 256>>>(x, w2, b2, 0, 1, 1);   // g_h1 -> g_feat
    k_norm<<<(BB*L + 255)/256, 256>>>();
    k_un<<<(BB*F*L + 255)/256, 256>>>();
    k_gemm_topk<<<dim3(64, BB), 256>>>();
    k_fold<<<dim3(16, 2, BB), 256>>>();
    k_tex<<<dim3(16, BB), 256>>>(wt1, bt1);
    k_final<<<dim3(16, BB), 256>>>(x, wt2, bt2, out);
}

// round 2
// speedup vs baseline: 2.2739x; 2.2739x over previous
#include <cuda_runtime.h>
#include <cstdint>

#define BB 2
#define C 64
#define H 64
#define W 64
#define L 4096   // H*W
#define F 576    // C*9
#define HP 66    // H+2 (reflect-padded)

#define KSPLIT 2
#define KEYS_PER_SPLIT (L / KSPLIT)
#define TILE_M 64
#define TILE_N 256
#define KTILE 16
#define NKT (F / KTILE)   // 36

typedef unsigned long long ull;

// ---------------- scratch (static device arrays; no allocation) ----------------
__device__ float g_xpad[BB*C*HP*HP];
__device__ float g_h1[BB*C*L];
__device__ float g_feat[BB*C*L];
__device__ float g_rnorm[BB*L];
__device__ float g_un[BB*F*L];             // [b][f][q]
__device__ float g_tvs[BB*KSPLIT*L*3];     // per-split top-3 values
__device__ int   g_tis[BB*KSPLIT*L*3];     // per-split top-3 indices
__device__ float g_tv[BB*L*3];             // merged top-3 values
__device__ int   g_ti[BB*L*3];             // merged top-3 indices
__device__ float g_Tcat[BB*2*C*L];
__device__ float g_tex[BB*C*L];

// ---------------- small PTX helpers ----------------
__device__ __forceinline__ ull dup2(float x) {
    ull r; unsigned xi = __float_as_uint(x);
    asm("mov.b64 %0, {%1,%1};" : "=l"(r) : "r"(xi));
    return r;
}
__device__ __forceinline__ ull pk2(float lo, float hi) {
    ull r;
    asm("mov.b64 %0, {%1,%2};" : "=l"(r)
        : "r"(__float_as_uint(lo)), "r"(__float_as_uint(hi)));
    return r;
}
__device__ __forceinline__ void fma2(ull& c, ull a, ull b) {
    asm("fma.rn.f32x2 %0, %1, %2, %0;" : "+l"(c) : "l"(a), "l"(b));
}
__device__ __forceinline__ void unpk(ull v, float& lo, float& hi) {
    unsigned a, b;
    asm("mov.b64 {%0,%1}, %2;" : "=r"(a), "=r"(b) : "l"(v));
    lo = __uint_as_float(a); hi = __uint_as_float(b);
}
#define CPA16(d, s) asm volatile("cp.async.cg.shared.global [%0], [%1], 16;" :: "r"(d), "l"(s))
#define CPCOMMIT()  asm volatile("cp.async.commit_group;")
#define CPWAITALL() asm volatile("cp.async.wait_all;")

// total-order comparator: larger value first, ties -> smaller index (lax.top_k)
__device__ __forceinline__ bool bet(float va, int ia, float vb, int ib) {
    return (va > vb) || (va == vb && ia < ib);
}
__device__ __forceinline__ void ins3(float v, int i,
                                     float& v0, int& i0, float& v1, int& i1,
                                     float& v2, int& i2) {
    if (bet(v, i, v2, i2)) {
        if (bet(v, i, v0, i0))      { v2=v1;i2=i1; v1=v0;i1=i0; v0=v;i0=i; }
        else if (bet(v, i, v1, i1)) { v2=v1;i2=i1; v1=v;i1=i; }
        else                        { v2=v;i2=i; }
    }
}

// ---------------- reflect pad ----------------
__global__ void k_xpad(const float* __restrict__ x) {
    int idx = blockIdx.x * blockDim.x + threadIdx.x;
    const int total = BB*C*HP*HP;
    if (idx >= total) return;
    int xx = idx % HP; int t = idx / HP;
    int yy = t % HP;   t /= HP;
    int c  = t % C;    int b = t / C;
    int sy = yy - 1; sy = sy < 0 ? -sy : (sy > H-1 ? 2*(H-1)-sy : sy);
    int sx = xx - 1; sx = sx < 0 ? -sx : (sx > W-1 ? 2*(W-1)-sx : sx);
    g_xpad[idx] = x[((b*C + c)*H + sy)*W + sx];
}

// ---------------- patch norms ----------------
__global__ void k_norm() {
    int idx = blockIdx.x * blockDim.x + threadIdx.x;
    if (idx >= BB*L) return;
    int b = idx / L, q = idx % L;
    int qy = q / W, qx = q % W;
    const float* base = &g_xpad[(size_t)b*C*HP*HP];
    float s = 0.f;
    for (int c = 0; c < C; c++) {
        const float* p = base + c*HP*HP + qy*HP + qx;
        #pragma unroll
        for (int i = 0; i < 3; i++)
            #pragma unroll
            for (int j = 0; j < 3; j++) { float v = p[i*HP + j]; s += v*v; }
    }
    float n = sqrtf(s);
    g_rnorm[idx] = 1.f / fmaxf(n, 1e-12f);
}

// ---------------- normalized unfold un[b][f][q] ----------------
__global__ void k_un() {
    int idx = blockIdx.x * blockDim.x + threadIdx.x;
    if (idx >= BB*F*L) return;
    int q = idx % L; int t = idx / L;
    int f = t % F;   int b = t / F;
    int c = f / 9, k = f % 9;
    int i = k / 3, j = k % 3;
    int qy = q / W, qx = q % W;
    float v = g_xpad[((b*C + c)*HP + qy + i)*HP + qx + j];
    g_un[idx] = v * g_rnorm[b*L + q];
}

// ---------------- fused Gram GEMM (fma.rn.f32x2) + register top-3 ----------------
// grid (L/TILE_M=64, KSPLIT=2, BB=2) = 256 blocks, 256 threads.
// Block: 64 queries x 2048 keys, tiles of 64x256, 8x8 microtile (col pairs).
__global__ void __launch_bounds__(256, 2) k_gemm_topk() {
    __shared__ float sA[2][KTILE*TILE_M];
    __shared__ float sB[2][KTILE*TILE_N];

    const int b = blockIdx.z, split = blockIdx.y;
    const int q0 = blockIdx.x * TILE_M;
    const int tid = threadIdx.x;
    const int ty = tid >> 5;          // warp id -> rows ty*8..ty*8+7
    const int tx = tid & 31;          // lane  -> cols {tx*4..+3, 128+tx*4..+3}
    const float* un = &g_un[(size_t)b*F*L];

    // global load mapping
    const int arow = tid >> 4, acol = (tid & 15) << 2;   // A: 16 rows x 16 float4
    const int brow = tid >> 6, bcol = (tid & 63) << 2;   // B: 4 row-groups x 64 float4
    const float* gA = un + (size_t)arow*L + q0 + acol;
    const float* gB = un + (size_t)brow*L + bcol;

    uint32_t sAd[2], sBd[2];
    sAd[0] = (uint32_t)__cvta_generic_to_shared(&sA[0][arow*TILE_M + acol]);
    sAd[1] = (uint32_t)__cvta_generic_to_shared(&sA[1][arow*TILE_M + acol]);
    sBd[0] = (uint32_t)__cvta_generic_to_shared(&sB[0][brow*TILE_N + bcol]);
    sBd[1] = (uint32_t)__cvta_generic_to_shared(&sB[1][brow*TILE_N + bcol]);

    float rv0=-2.f, rv1=-2.f, rv2=-2.f;
    int   ri0=0x7fffffff, ri1=0x7fffffff, ri2=0x7fffffff;

    #define PF(kt, bf, n0) {                                                   \
        int kk = (kt)*KTILE;                                                   \
        CPA16(sAd[bf], gA + (size_t)kk*L);                                     \
        const float* gb = gB + (n0) + (size_t)kk*L;                            \
        CPA16(sBd[bf],                   gb);                                  \
        CPA16(sBd[bf] + 4*TILE_N*4,      gb + 4*(size_t)L);                    \
        CPA16(sBd[bf] + 8*TILE_N*4,      gb + 8*(size_t)L);                    \
        CPA16(sBd[bf] + 12*TILE_N*4,     gb + 12*(size_t)L);                   \
    }

    for (int nt = 0; nt < KEYS_PER_SPLIT/TILE_N; nt++) {
        const int n0 = split*KEYS_PER_SPLIT + nt*TILE_N;

        ull acc[8][4];
        #pragma unroll
        for (int i = 0; i < 8; i++)
            #pragma unroll
            for (int j = 0; j < 4; j++) acc[i][j] = 0ull;

        PF(0, 0, n0); CPCOMMIT();

        for (int kt = 0; kt < NKT; kt++) {
            CPWAITALL();
            __syncthreads();
            if (kt + 1 < NKT) { PF(kt+1, (kt+1)&1, n0); CPCOMMIT(); }
            const float* A  = sA[kt & 1];
            const float* Bt = sB[kt & 1];
            #pragma unroll
            for (int p = 0; p < KTILE; p++) {
                float4 alo = *(const float4*)&A[p*TILE_M + ty*8];
                float4 ahi = *(const float4*)&A[p*TILE_M + ty*8 + 4];
                float4 bl  = *(const float4*)&Bt[p*TILE_N + tx*4];
                float4 bh  = *(const float4*)&Bt[p*TILE_N + 128 + tx*4];
                ull b0 = pk2(bl.x, bl.y), b1 = pk2(bl.z, bl.w);
                ull b2 = pk2(bh.x, bh.y), b3 = pk2(bh.z, bh.w);
                float av[8] = {alo.x,alo.y,alo.z,alo.w,ahi.x,ahi.y,ahi.z,ahi.w};
                #pragma unroll
                for (int i = 0; i < 8; i++) {
                    ull ad = dup2(av[i]);
                    fma2(acc[i][0], ad, b0);
                    fma2(acc[i][1], ad, b1);
                    fma2(acc[i][2], ad, b2);
                    fma2(acc[i][3], ad, b3);
                }
            }
        }

        // register top-3 merge for this 64x256 tile
        #pragma unroll
        for (int i = 0; i < 8; i++) {
            float tv0=-2.f, tv1=-2.f, tv2=-2.f;
            int   ti0=0x7fffffff, ti1=0x7fffffff, ti2=0x7fffffff;
            #pragma unroll
            for (int jp = 0; jp < 4; jp++) {
                float lo, hi;
                unpk(acc[i][jp], lo, hi);
                int cbase = n0 + ((jp >> 1) ? 128 : 0) + tx*4 + ((jp & 1) << 1);
                ins3(lo, cbase,   tv0,ti0, tv1,ti1, tv2,ti2);
                ins3(hi, cbase+1, tv0,ti0, tv1,ti1, tv2,ti2);
            }
            #pragma unroll
            for (int off = 16; off; off >>= 1) {
                float w0 = __shfl_xor_sync(0xffffffffu, tv0, off);
                int   j0 = __shfl_xor_sync(0xffffffffu, ti0, off);
                float w1 = __shfl_xor_sync(0xffffffffu, tv1, off);
                int   j1 = __shfl_xor_sync(0xffffffffu, ti1, off);
                float w2 = __shfl_xor_sync(0xffffffffu, tv2, off);
                int   j2 = __shfl_xor_sync(0xffffffffu, ti2, off);
                ins3(w0,j0, tv0,ti0, tv1,ti1, tv2,ti2);
                ins3(w1,j1, tv0,ti0, tv1,ti1, tv2,ti2);
                ins3(w2,j2, tv0,ti0, tv1,ti1, tv2,ti2);
            }
            if (tx == i) {
                ins3(tv0,ti0, rv0,ri0, rv1,ri1, rv2,ri2);
                ins3(tv1,ti1, rv0,ri0, rv1,ri1, rv2,ri2);
                ins3(tv2,ti2, rv0,ri0, rv1,ri1, rv2,ri2);
            }
        }
    }
    #undef PF

    if (tx < 8) {
        int q = q0 + ty*8 + tx;
        size_t base = ((size_t)(b*KSPLIT + split)*L + q)*3;
        g_tvs[base+0] = rv0; g_tvs[base+1] = rv1; g_tvs[base+2] = rv2;
        g_tis[base+0] = ri0; g_tis[base+1] = ri1; g_tis[base+2] = ri2;
    }
}

// ---------------- merge the KSPLIT partial top-3s ----------------
__global__ void k_topk_merge() {
    int idx = blockIdx.x * blockDim.x + threadIdx.x;
    if (idx >= BB*L) return;
    int b = idx / L, q = idx % L;
    size_t s0 = ((size_t)(b*KSPLIT + 0)*L + q)*3;
    size_t s1 = ((size_t)(b*KSPLIT + 1)*L + q)*3;
    float v0 = g_tvs[s0], v1 = g_tvs[s0+1], v2 = g_tvs[s0+2];
    int   i0 = g_tis[s0], i1 = g_tis[s0+1], i2 = g_tis[s0+2];
    ins3(g_tvs[s1],   g_tis[s1],   v0,i0, v1,i1, v2,i2);
    ins3(g_tvs[s1+1], g_tis[s1+1], v0,i0, v1,i1, v2,i2);
    ins3(g_tvs[s1+2], g_tis[s1+2], v0,i0, v1,i1, v2,i2);
    size_t d = (size_t)(b*L + q)*3;
    g_tv[d+0] = v0; g_tv[d+1] = v1; g_tv[d+2] = v2;
    g_ti[d+0] = i0; g_ti[d+1] = i1; g_ti[d+2] = i2;
}

// ---------------- 3x3 conv (zero pad), optional relu ----------------
__global__ void __launch_bounds__(256) k_conv3x3(
    const float* __restrict__ xin, const float* __restrict__ w,
    const float* __restrict__ bias, int relu, int insel, int outsel)
{
    __shared__ float s_in[16][324];
    __shared__ float s_w[16][144];

    const float* in = insel ? g_h1 : xin;
    float* out = outsel ? g_feat : g_h1;

    int tile = blockIdx.x;
    int oc0  = blockIdx.y * 16;
    int b    = blockIdx.z;
    int ty0 = (tile / 4) * 16, tx0 = (tile % 4) * 16;
    int tid = threadIdx.x;
    int py = tid / 16, px = tid % 16;

    float acc[16];
    #pragma unroll
    for (int o = 0; o < 16; o++) acc[o] = bias[oc0 + o];

    for (int icc = 0; icc < 4; icc++) {
        for (int i = tid; i < 16*324; i += 256) {
            int ic = i / 324; int rem = i % 324;
            int yy = rem / 18, xx = rem % 18;
            int gy = ty0 + yy - 1, gx = tx0 + xx - 1;
            float v = 0.f;
            if (gy >= 0 && gy < H && gx >= 0 && gx < W)
                v = in[((b*C + icc*16 + ic)*H + gy)*W + gx];
            s_in[ic][rem] = v;
        }
        for (int i = tid; i < 16*144; i += 256) {
            int o = i / 144; int rem = i % 144;
            s_w[o][rem] = w[((oc0 + o)*C + icc*16 + rem/9)*9 + rem%9];
        }
        __syncthreads();

        for (int ic = 0; ic < 16; ic++) {
            float v[9];
            #pragma unroll
            for (int dy = 0; dy < 3; dy++)
                #pragma unroll
                for (int dx = 0; dx < 3; dx++)
                    v[dy*3+dx] = s_in[ic][(py+dy)*18 + px+dx];
            #pragma unroll
            for (int o = 0; o < 16; o++) {
                float a = acc[o];
                #pragma unroll
                for (int k = 0; k < 9; k++) a += v[k] * s_w[o][ic*9 + k];
                acc[o] = a;
            }
        }
        __syncthreads();
    }
    int gy = ty0 + py, gx = tx0 + px;
    #pragma unroll
    for (int o = 0; o < 16; o++) {
        float v = acc[o];
        if (relu) v = fmaxf(v, 0.f);
        out[((b*C + oc0 + o)*H + gy)*W + gx] = v;
    }
}

// ---------------- gather + fold3 + scale ----------------
__global__ void k_fold() {
    int tile = blockIdx.x;
    int tt   = blockIdx.y;
    int b    = blockIdx.z;
    int tid = threadIdx.x;
    int py = tid / 16, px = tid % 16;
    int y = (tile / 4)*16 + py, x = (tile % 4)*16 + px;
    int q = y*W + x;
    int slot = tt + 1;

    float S = g_tv[(b*L + q)*3 + slot];

    int off[9];
    #pragma unroll
    for (int i = 0; i < 3; i++) {
        #pragma unroll
        for (int j = 0; j < 3; j++) {
            int h = y + 1 - i, w = x + 1 - j;
            int o = -1;
            if (h >= 0 && h < H && w >= 0 && w < W) {
                int r = g_ti[(b*L + h*W + w)*3 + slot];
                int ry = r / W, rx = r % W;
                o = (ry + i)*HP + (rx + j);
            }
            off[i*3 + j] = o;
        }
    }
    float scale = S * (1.f/9.f);
    const float* xp = &g_xpad[(size_t)b*C*HP*HP];
    float* out = &g_Tcat[(size_t)((b*2 + tt)*C)*L];
    for (int c = 0; c < C; c++) {
        const float* pc = xp + c*HP*HP;
        float s = 0.f;
        #pragma unroll
        for (int k = 0; k < 9; k++)
            if (off[k] >= 0) s += pc[off[k]];
        out[c*L + q] = s * scale;
    }
}

// ---------------- texture 1x1 conv: (64 x 128) ----------------
__global__ void __launch_bounds__(256) k_tex(const float* __restrict__ wt1,
                                             const float* __restrict__ bt1) {
    __shared__ float s_w[64*128];
    for (int i = threadIdx.x; i < 64*128; i += 256) s_w[i] = wt1[i];
    __syncthreads();
    int b = blockIdx.y;
    int p = blockIdx.x*256 + threadIdx.x;
    const float* in = &g_Tcat[(size_t)b*128*L];
    float acc[64];
    #pragma unroll
    for (int o = 0; o < 64; o++) acc[o] = bt1[o];
    for (int k = 0; k < 128; k++) {
        float v = in[k*L + p];
        #pragma unroll
        for (int o = 0; o < 64; o++) acc[o] += v * s_w[o*128 + k];
    }
    float* out = &g_tex[(size_t)b*64*L];
    #pragma unroll
    for (int o = 0; o < 64; o++) out[o*L + p] = acc[o];
}

// ---------------- final 1x1 conv over [feature, x, texture] ----------------
__global__ void __launch_bounds__(256) k_final(const float* __restrict__ x,
                                               const float* __restrict__ wt2,
                                               const float* __restrict__ bt2,
                                               float* __restrict__ out) {
    __shared__ float s_w[64*64];
    int b = blockIdx.y;
    int p = blockIdx.x*256 + threadIdx.x;
    float acc[64];
    #pragma unroll
    for (int o = 0; o < 64; o++) acc[o] = bt2[o];

    const float* srcs[3] = { &g_feat[(size_t)b*64*L], x + (size_t)b*64*L, &g_tex[(size_t)b*64*L] };
    for (int g = 0; g < 3; g++) {
        __syncthreads();
        for (int i = threadIdx.x; i < 64*64; i += 256) {
            int o = i / 64, k = i % 64;
            s_w[i] = wt2[o*192 + g*64 + k];
        }
        __syncthreads();
        const float* in = srcs[g];
        for (int k = 0; k < 64; k++) {
            float v = in[k*L + p];
            #pragma unroll
            for (int o = 0; o < 64; o++) acc[o] += v * s_w[o*64 + k];
        }
    }
    #pragma unroll
    for (int o = 0; o < 64; o++) out[((size_t)b*64 + o)*L + p] = acc[o];
}

// ---------------- host launcher ----------------
extern "C" void kernel_launch(void* const* d_in, const int* in_sizes, int n_in,
                              void* d_out, int out_size) {
    const float* x   = (const float*)d_in[0];
    const float* w1  = (const float*)d_in[1];
    const float* b1  = (const float*)d_in[2];
    const float* w2  = (const float*)d_in[3];
    const float* b2  = (const float*)d_in[4];
    const float* wt1 = (const float*)d_in[5];
    const float* bt1 = (const float*)d_in[6];
    const float* wt2 = (const float*)d_in[7];
    const float* bt2 = (const float*)d_in[8];
    float* out = (float*)d_out;

    k_xpad<<<(BB*C*HP*HP + 255)/256, 256>>>(x);
    k_norm<<<(BB*L + 255)/256, 256>>>();
    k_un<<<(BB*F*L + 255)/256, 256>>>();
    k_gemm_topk<<<dim3(L/TILE_M, KSPLIT, BB), 256>>>();
    k_topk_merge<<<(BB*L + 255)/256, 256>>>();
    k_conv3x3<<<dim3(16, 4, BB), 256>>>(x, w1, b1, 1, 0, 0);
    k_conv3x3<<<dim3(16, 4, BB), 256>>>(x, w2, b2, 0, 1, 1);
    k_fold<<<dim3(16, 2, BB), 256>>>();
    k_tex<<<dim3(16, BB), 256>>>(wt1, bt1);
    k_final<<<dim3(16, BB), 256>>>(x, wt2, bt2, out);
}